// round 17
// baseline (speedup 1.0000x reference)
#include <cuda_runtime.h>

// DTW loss: B=16, C=8, T=512 -> 128 independent 512x512 DTW DPs.
// One block (128 thr / 4 warps) per pair; lane owns 4 DP cols; superstep =
// 4 rows x 4 cols; sigma = lane + 39*warp; groups of 4 ss, one combined
// sentinel check; shfls interleaved after each row; BIG-fill handoff
// (identical structure to R13 @ 28.7us).
// R17: TROPICAL LOOKAHEAD-2 per row. t_k = d_k + min(t_{k-1}, m_k) is a
//   (min,+) recurrence: with s_k = d_k + m_k,
//     t1 = min(L + (d0+d1), min(s0+d1, s1))     [chain: FADD+FMNMX]
//     t3 = min(t1 + (d2+d3), min(s2+d3, s3))    [chain: FADD+FMNMX]
//   so the on-chain path/row halves (40 -> ~18 cyc); D/Q/s/m and t0/t2 are
//   off-chain and fill the ~120 cyc/ss of idle in-order-issue slots.
// Fill stays bit-exact BIG (1e30 + small == 1e30 fp32); drain >= 0/finite.

#define TT    512
#define IWS   39
#define SIGMX (31 + 3 * IWS)       // 148
#define NSS   (TT / 4 + SIGMX)     // 276 supersteps
#define NG    (NSS / 4)            // 69 groups
#define GUARD 8
#define REG   (GUARD + NSS)
#define BIGF  1e30f

__device__ float        g_partials[128];
__device__ unsigned int g_counter = 0;

// One DP row with lookahead-2. L_ = left (dtw[i][j0-1]); lp_ = left of the
// previous row (diag for col 0). Updates up0..3; row carry -> cO_.
#define ROW_LA(xi_, L_, lp_, cO_) do {                                         \
    const float d0 = fabsf((xi_) - y0);                                        \
    const float d1 = fabsf((xi_) - y1);                                        \
    const float d2 = fabsf((xi_) - y2);                                        \
    const float d3 = fabsf((xi_) - y3);                                        \
    const float m0 = fminf(up0, (lp_));                                        \
    const float m1 = fminf(up1, up0);                                          \
    const float m2 = fminf(up2, up1);                                          \
    const float m3 = fminf(up3, up2);                                          \
    const float s0 = d0 + m0;                                                  \
    const float s1 = d1 + m1;                                                  \
    const float s2 = d2 + m2;                                                  \
    const float s3 = d3 + m3;                                                  \
    const float D01 = d0 + d1;                                                 \
    const float D23 = d2 + d3;                                                 \
    const float Q1 = fminf(s0 + d1, s1);                                       \
    const float Q3 = fminf(s2 + d3, s3);                                       \
    const float t1v = fminf((L_) + D01, Q1);                                   \
    const float t0v = fminf((L_) + d0, s0);                                    \
    const float t2v = fminf(t1v + d2, s2);                                     \
    const float t3v = fminf(t1v + D23, Q3);                                    \
    up0 = t0v; up1 = t1v; up2 = t2v; up3 = t3v; cO_ = t3v;                     \
} while (0)

// One superstep. Consumes L0..L3 (+ lvprev); produces next-ss L's from the
// interleaved shfls (lane0 <- hq_, the cross-warp slot for the NEXT ss).
#define SSP(xq_, hq_, k_) do {                                                 \
    ROW_LA(xq_.x, L0, lvprev, c0);                                             \
    float n0 = __shfl_up_sync(0xffffffffu, c0, 1);                             \
    ROW_LA(xq_.y, L1, L0, c1);                                                 \
    float n1 = __shfl_up_sync(0xffffffffu, c1, 1);                             \
    ROW_LA(xq_.z, L2, L1, c2);                                                 \
    float n2 = __shfl_up_sync(0xffffffffu, c2, 1);                             \
    ROW_LA(xq_.w, L3, L2, c3);                                                 \
    float n3 = __shfl_up_sync(0xffffffffu, c3, 1);                             \
    if (lane == 0) { n0 = hq_.x; n1 = hq_.y; n2 = hq_.z; n3 = hq_.w; }         \
    if (prod) qq[k_] = make_float4(c0, c1, c2, c3);                            \
    lvprev = L3;                                                               \
    L0 = n0; L1 = n1; L2 = n2; L3 = n3;                                        \
} while (0)

// Cold path: volatile re-poll of one slot until its .w leaves sentinel.
#define FIXSLOT(h_, k_) do {                                                   \
    volatile float* vp = (volatile float*)(pp + (k_));                         \
    float w = vp[3];                                                           \
    while (w < 0.0f) { w = vp[3]; }                                            \
    (h_).x = vp[0]; (h_).y = vp[1]; (h_).z = vp[2]; (h_).w = w;                \
} while (0)

__global__ __launch_bounds__(128, 1)
void dtw_fused_kernel(const float* __restrict__ inputs,
                      const float* __restrict__ targets,
                      float* __restrict__ out) {
    const int p    = blockIdx.x;
    const float* x = inputs + p * TT;
    const int tid  = threadIdx.x;
    const int lane = tid & 31;
    const int warp = tid >> 5;
    const int sig  = lane + IWS * warp;

    __shared__ float4 xsbuf[SIGMX + TT / 4 + SIGMX];      // 424 float4
    __shared__ float4 handbuf[4 + 3 * REG];               // 856 float4

    {   // init smem
        float* xf = (float*)xsbuf;
        const int PRE = SIGMX * 4;
        for (int k = tid; k < PRE; k += 128) xf[k] = 0.0f;
        for (int k = tid; k < PRE; k += 128) xf[PRE + TT + k] = 0.0f;
        for (int k = tid; k < TT;  k += 128) xf[PRE + k] = x[k];
        float* hf = (float*)handbuf;
        for (int k = tid; k < (4 + 3 * REG) * 4; k += 128) hf[k] = -1.0f;
    }
    __syncthreads();
    {   // guards -> BIG (warp0 block + each region's 8-slot prefix)
        float* hf = (float*)handbuf;
        for (int k = tid; k < 16; k += 128) hf[k] = BIGF;
        for (int r = 0; r < 3; ++r)
            for (int k = tid; k < GUARD * 4; k += 128)
                hf[(4 + r * REG) * 4 + k] = BIGF;
    }

    const float4 yq = ((const float4*)(targets + p * TT))[tid];
    const float y0 = yq.x, y1 = yq.y, y2 = yq.z, y3 = yq.w;

    float up0 = BIGF, up1 = BIGF, up2 = BIGF, up3 = BIGF;
    float c0 = BIGF, c1 = BIGF, c2 = BIGF, c3 = BIGF;
    float L0 = BIGF, L1 = BIGF, L2 = BIGF, L3 = BIGF;     // lefts for ss 0
    float lvprev = (tid == 0) ? 0.0f : BIGF;              // dtw[0][0] seed

    const bool prod = (lane == 31 && warp < 3);
    // Consumer base: region start (logical slot -8) shifted +1 (L's made at
    // ss t feed ss t+1 -> slot t-7). warp0 frozen on its BIG block.
    float4* pp = (warp > 0) ? (handbuf + 4 + (warp - 1) * REG + 1) : handbuf;
    const int pinc = (warp > 0) ? 4 : 0;
    float4* qq = handbuf + 4 + warp * REG + GUARD;        // producer slot 0
    const float4* xp = xsbuf + SIGMX - sig;

    __syncthreads();

    for (int g = 0; g < NG; ++g) {
        float4 hq0 = pp[0], hq1 = pp[1], hq2 = pp[2], hq3 = pp[3];
        if ((hq0.w < 0.0f) | (hq1.w < 0.0f) | (hq2.w < 0.0f) | (hq3.w < 0.0f)) {
            FIXSLOT(hq0, 0); FIXSLOT(hq1, 1); FIXSLOT(hq2, 2); FIXSLOT(hq3, 3);
        }

        const float4 xq0 = xp[0], xq1 = xp[1], xq2 = xp[2], xq3 = xp[3];

        SSP(xq0, hq0, 0);
        SSP(xq1, hq1, 1);
        SSP(xq2, hq2, 2);
        SSP(xq3, hq3, 3);

        pp += pinc; qq += 4; xp += 4;
    }

    // tid 127 (sig = 148): last valid ss = 275 = NSS-1; c3 = dtw[512][512].
    if (tid == 127) {
        g_partials[p] = c3 * (1.0f / (float)TT);
        __threadfence();
        unsigned int old = atomicAdd(&g_counter, 1u);
        if (old == 127u) {
            volatile float* gp = g_partials;
            float sum = 0.0f;
            #pragma unroll 16
            for (int k = 0; k < 128; ++k) sum += gp[k];
            out[0] = sum * 0.125f;                       // (1/C) * sum_b
            *(volatile unsigned int*)&g_counter = 0;     // reset for replay
        }
    }
}

extern "C" void kernel_launch(void* const* d_in, const int* in_sizes, int n_in,
                              void* d_out, int out_size) {
    const float* inputs  = (const float*)d_in[0];
    const float* targets = (const float*)d_in[1];
    float* out = (float*)d_out;
    (void)in_sizes; (void)n_in; (void)out_size;

    dtw_fused_kernel<<<128, 128>>>(inputs, targets, out);
}